// round 17
// baseline (speedup 1.0000x reference)
#include <cuda_runtime.h>
#include <cstdint>

// Problem constants
#define B_TOTAL  128
#define C_IN     32
#define C_OUT    8
#define S_TOTAL  8192

// Tiling
#define S_TILE    32     // s-values per block = 8 float4 groups
#define SG        8      // float4 groups per block
#define B_PER_BLK 32     // batches per block (2 per thread)
#define THREADS   128
#define DEPTH     5      // cp.async pipeline stages for x
#define DIST      4      // issue distance (j+DIST), wait_group DIST

// Smem layout (bytes): w2s 32K | wss 4K | xs 5*4K = 56K total
#define SMEM_W2   0
#define SMEM_WS   32768
#define SMEM_X    36864
#define SMEM_TOT  57344
#define XSTAGE_B  4096   // one stage: 32 bt-slots * 8 sg * 16 B

typedef unsigned long long ull;

// ---------------------------------------------------------------------------
// helpers
// ---------------------------------------------------------------------------
__device__ __forceinline__ float tanh_fast(float x) {
    float y;
    asm("tanh.approx.f32 %0, %1;" : "=f"(y) : "f"(x));
    return y;
}

__device__ __forceinline__ float4 ld4(const float* p) {
    return *reinterpret_cast<const float4*>(p);
}

__device__ __forceinline__ float4 tanh4_of_prod(float4 a, float4 b) {
    float4 r;
    r.x = tanh_fast(a.x * b.x);
    r.y = tanh_fast(a.y * b.y);
    r.z = tanh_fast(a.z * b.z);
    r.w = tanh_fast(a.w * b.w);
    return r;
}

// packed f32x2 FMA (Blackwell FFMA2, PTX-only)
__device__ __forceinline__ void fma2p(ull& acc, ull h, ull w) {
    asm("fma.rn.f32x2 %0, %1, %2, %0;" : "+l"(acc) : "l"(h), "l"(w));
}

struct u2 { ull lo, hi; };   // 4 packed floats (== float4 bits)

__device__ __forceinline__ void fma4p(u2& acc, const u2& h, const u2& w) {
    fma2p(acc.lo, h.lo, w.lo);
    fma2p(acc.hi, h.hi, w.hi);
}

// cp.async 16B global -> shared (LDGSTS)
__device__ __forceinline__ void cp16(uint32_t dst, const float* src) {
    asm volatile("cp.async.ca.shared.global [%0], [%1], 16;"
                 :: "r"(dst), "l"(src) : "memory");
}
#define CP_COMMIT() asm volatile("cp.async.commit_group;" ::: "memory")
#define CP_WAIT()   asm volatile("cp.async.wait_group %0;" :: "n"(DIST) : "memory")

// ---------------------------------------------------------------------------
// Single fused kernel: ws reduction (preamble) + stage1 + stage2.
// R16 structure + 5-stage / distance-4 cp.async pipeline for x
// (covers the full ~600-cycle DRAM latency).
// ---------------------------------------------------------------------------
__global__ void __launch_bounds__(THREADS, 4) fused_kernel(
    const float* __restrict__ x,     // [B][C_IN][S]
    const float* __restrict__ w1,    // [C_IN][C_IN][S]
    const float* __restrict__ w2,    // [C_OUT][C_IN][S]
    const float* __restrict__ bias,  // [C_OUT][S]
    float* __restrict__ out)         // [B][C_OUT][S]
{
    extern __shared__ char smem[];
    float4* w2s = reinterpret_cast<float4*>(smem + SMEM_W2);  // 2048 f4
    float4* wss = reinterpret_cast<float4*>(smem + SMEM_WS);  //  256 f4

    const int t     = threadIdx.x;
    const int sBase = blockIdx.x * S_TILE;
    const int bt    = t >> 3;                  // 0..15
    const int sg    = t & 7;                   // 0..7
    const int b0    = blockIdx.y * B_PER_BLK + bt;
    const int b1    = b0 + 16;

    const float* xp0 = x + ((size_t)b0 * C_IN) * S_TOTAL + sBase + sg * 4;
    const float* xp1 = x + ((size_t)b1 * C_IN) * S_TOTAL + sBase + sg * 4;

    // per-thread stage-0 write address (stage stride XSTAGE_B, b1 slot +2048)
    const uint32_t xw =
        (uint32_t)__cvta_generic_to_shared(smem + SMEM_X) + bt * 128 + sg * 16;

    // ---- x pipeline prologue: stages 0..DIST-1 (overlap the preamble) ----
#pragma unroll
    for (int j = 0; j < DIST; j++) {
        uint32_t w = xw + j * XSTAGE_B;
        cp16(w,        xp0 + (size_t)j * S_TOTAL);
        cp16(w + 2048, xp1 + (size_t)j * S_TOTAL);
        CP_COMMIT();
    }

    // ---- preamble A: w2 tile -> smem ----
#pragma unroll
    for (int k = 0; k < (C_OUT * C_IN * SG) / THREADS; k++) {   // 16 iters
        int idx = t + k * THREADS;
        int row = idx >> 3;           // o*32 + j
        int sgl = idx & 7;
        w2s[idx] = ld4(w2 + (size_t)row * S_TOTAL + sBase + sgl * 4);
    }

    // ---- preamble B: ws tile computed from w1 (reduction over i) ----
#pragma unroll
    for (int k = 0; k < (C_IN * SG) / THREADS; k++) {           // 2 iters
        int idx = t + k * THREADS;
        int j   = idx >> 3;
        int sgl = idx & 7;
        const float* p = w1 + (size_t)j * S_TOTAL + sBase + sgl * 4;
        float4 a = make_float4(0.f, 0.f, 0.f, 0.f);
#pragma unroll 8
        for (int i = 0; i < C_IN; i++) {
            float4 v = ld4(p + (size_t)i * C_IN * S_TOTAL);
            a.x += v.x; a.y += v.y; a.z += v.z; a.w += v.w;
        }
        wss[idx] = a;
    }
    __syncthreads();

    // ---- accumulators init from bias (same bias for both batches) ----
    u2 acc0[C_OUT], acc1[C_OUT];
#pragma unroll
    for (int o = 0; o < C_OUT; o++) {
        float4 bv = ld4(bias + (size_t)o * S_TOTAL + sBase + sg * 4);
        acc0[o] = *reinterpret_cast<const u2*>(&bv);
        acc1[o] = acc0[o];
    }

    // ---- main loop over j with 5-deep cp.async pipeline ----
    int st = 0;                       // stage holding x(j)
#pragma unroll 1
    for (int j = 0; j < C_IN; j++) {
        // issue x(j+DIST) into the stage freed DEPTH-DIST iters ago
        if (j + DIST < C_IN) {
            int st2 = st + DIST; if (st2 >= DEPTH) st2 -= DEPTH;
            uint32_t w = xw + st2 * XSTAGE_B;
            cp16(w,        xp0 + (size_t)(j + DIST) * S_TOTAL);
            cp16(w + 2048, xp1 + (size_t)(j + DIST) * S_TOTAL);
        }
        CP_COMMIT();                  // empty in the DIST tail iterations
        CP_WAIT();                    // guarantees group g(j) complete

        const float4* xsp =
            reinterpret_cast<const float4*>(smem + SMEM_X + st * XSTAGE_B);
        float4 xv0 = xsp[bt * SG + sg];
        float4 xv1 = xsp[(bt + 16) * SG + sg];
        float4 wsv = wss[j * SG + sg];
        float4 h0f = tanh4_of_prod(xv0, wsv);
        float4 h1f = tanh4_of_prod(xv1, wsv);
        u2 h0 = *reinterpret_cast<const u2*>(&h0f);
        u2 h1 = *reinterpret_cast<const u2*>(&h1f);
#pragma unroll
        for (int o = 0; o < C_OUT; o++) {
            u2 w = *reinterpret_cast<const u2*>(&w2s[(o * C_IN + j) * SG + sg]);
            fma4p(acc0[o], h0, w);
            fma4p(acc1[o], h1, w);
        }
        st++; if (st >= DEPTH) st = 0;
    }

    // ---- epilogue: outer tanh (approx) + store (both batches) ----
    float* op0 = out + ((size_t)b0 * C_OUT) * S_TOTAL + sBase + sg * 4;
    float* op1 = out + ((size_t)b1 * C_OUT) * S_TOTAL + sBase + sg * 4;
#pragma unroll
    for (int o = 0; o < C_OUT; o++) {
        float4 a0 = *reinterpret_cast<const float4*>(&acc0[o]);
        float4 ov;
        ov.x = tanh_fast(a0.x);
        ov.y = tanh_fast(a0.y);
        ov.z = tanh_fast(a0.z);
        ov.w = tanh_fast(a0.w);
        *reinterpret_cast<float4*>(op0 + (size_t)o * S_TOTAL) = ov;
        float4 a1 = *reinterpret_cast<const float4*>(&acc1[o]);
        float4 ov1;
        ov1.x = tanh_fast(a1.x);
        ov1.y = tanh_fast(a1.y);
        ov1.z = tanh_fast(a1.z);
        ov1.w = tanh_fast(a1.w);
        *reinterpret_cast<float4*>(op1 + (size_t)o * S_TOTAL) = ov1;
    }
}

// ---------------------------------------------------------------------------
// launch
// ---------------------------------------------------------------------------
extern "C" void kernel_launch(void* const* d_in, const int* in_sizes, int n_in,
                              void* d_out, int out_size) {
    const float* x    = (const float*)d_in[0];
    const float* w1   = (const float*)d_in[1];
    const float* w2   = (const float*)d_in[2];
    const float* bias = (const float*)d_in[3];
    float* out = (float*)d_out;

    // 56 KB dynamic smem (> 48 KB static limit); idempotent, capture-safe
    cudaFuncSetAttribute(fused_kernel,
                         cudaFuncAttributeMaxDynamicSharedMemorySize, SMEM_TOT);

    dim3 grid(S_TOTAL / S_TILE, B_TOTAL / B_PER_BLK);   // (256, 4) = 1024 blocks
    fused_kernel<<<grid, THREADS, SMEM_TOT>>>(x, w1, w2, bias, out);
}